// round 1
// baseline (speedup 1.0000x reference)
#include <cuda_runtime.h>
#include <math.h>

#define HW     128
#define NPIX   (HW*HW)        // 16384
#define BSZ    128
#define NIMG   256
#define KSPLIT 16
#define PITCH  129            // smem row pitch in float2 (conflict padding)

// ---------------- device scratch (static, allocation-free) ----------------
__device__ float  g_norm[NIMG];                   // ||a_i||^2 (0..127), ||b_j||^2 (128..255)
__device__ float  g_dot_part[KSPLIT*BSZ*BSZ];     // K-split partial dot products
__device__ float  g_dist[BSZ*BSZ];                // Dist matrix (after sqrt)
__device__ float  g_lse[BSZ];                     // per-row logsumexp of Dist
__device__ float  g_psd[NIMG*NPIX];               // per-image |FFT|^2  (16 MB)
__device__ double g_red_log[128];                 // partial sums of log(avgpsd)
__device__ double g_red_avg[128];                 // partial sums of avgpsd

// ---------------- squared norms of every image ----------------
__global__ void norm_kernel(const float* __restrict__ x1, const float* __restrict__ x2) {
    int b = blockIdx.x;
    const float* src = (b < BSZ) ? (x1 + (size_t)b*NPIX) : (x2 + (size_t)(b-BSZ)*NPIX);
    float s = 0.f;
    for (int i = threadIdx.x; i < NPIX; i += blockDim.x) { float v = src[i]; s += v*v; }
    __shared__ float red[256];
    red[threadIdx.x] = s; __syncthreads();
    for (int off = 128; off > 0; off >>= 1) {
        if (threadIdx.x < off) red[threadIdx.x] += red[threadIdx.x + off];
        __syncthreads();
    }
    if (threadIdx.x == 0) g_norm[b] = red[0];
}

// ---------------- dot(a_i, b_j): 128x128x16384 fp32 GEMM, K-split ----------------
// grid (4,4,KSPLIT), block 64 threads (8x8), 4x4 micro-tile -> 32x32 tile/block
__global__ void dot_kernel(const float* __restrict__ A, const float* __restrict__ B) {
    __shared__ float As[32][33];
    __shared__ float Bs[32][33];
    int tid = threadIdx.x;
    int tx = tid & 7, ty = tid >> 3;
    int row0 = blockIdx.y * 32, col0 = blockIdx.x * 32;
    int kb = blockIdx.z * (NPIX / KSPLIT);          // 1024-wide K chunk

    float acc[4][4];
#pragma unroll
    for (int r = 0; r < 4; r++)
#pragma unroll
        for (int c = 0; c < 4; c++) acc[r][c] = 0.f;

    for (int kt = 0; kt < 32; kt++) {
        int k0 = kb + kt * 32;
#pragma unroll
        for (int l = tid; l < 1024; l += 64) {
            int r = l >> 5, kk = l & 31;
            As[r][kk] = A[(size_t)(row0 + r) * NPIX + k0 + kk];
            Bs[r][kk] = B[(size_t)(col0 + r) * NPIX + k0 + kk];
        }
        __syncthreads();
#pragma unroll
        for (int kk = 0; kk < 32; kk++) {
            float ra[4], rb[4];
#pragma unroll
            for (int r = 0; r < 4; r++) ra[r] = As[ty*4 + r][kk];
#pragma unroll
            for (int c = 0; c < 4; c++) rb[c] = Bs[tx*4 + c][kk];
#pragma unroll
            for (int r = 0; r < 4; r++)
#pragma unroll
                for (int c = 0; c < 4; c++) acc[r][c] += ra[r] * rb[c];
        }
        __syncthreads();
    }
#pragma unroll
    for (int r = 0; r < 4; r++)
#pragma unroll
        for (int c = 0; c < 4; c++)
            g_dot_part[(size_t)blockIdx.z*BSZ*BSZ + (row0 + ty*4 + r)*BSZ + (col0 + tx*4 + c)] = acc[r][c];
}

// ---------------- Dist + per-row logsumexp (fused; one block per row) ----------------
__global__ void dist_lse_kernel() {
    int i = blockIdx.x, j = threadIdx.x;
    float dot = 0.f;
#pragma unroll
    for (int s = 0; s < KSPLIT; s++) dot += g_dot_part[s*BSZ*BSZ + i*BSZ + j];
    float d2 = g_norm[i] + g_norm[BSZ + j] - 2.f * dot;
    float d = sqrtf(fmaxf(d2, 0.f));
    g_dist[i*BSZ + j] = d;

    __shared__ float red[BSZ];
    red[j] = d; __syncthreads();
    for (int off = 64; off > 0; off >>= 1) {
        if (j < off) red[j] = fmaxf(red[j], red[j + off]);
        __syncthreads();
    }
    float mx = red[0]; __syncthreads();
    red[j] = expf(d - mx); __syncthreads();
    for (int off = 64; off > 0; off >>= 1) {
        if (j < off) red[j] += red[j + off];
        __syncthreads();
    }
    if (j == 0) g_lse[i] = mx + logf(red[0]);
}

// ---------------- 2D FFT (radix-2 DIF, bit-reversed output) + |F|^2 ----------------
// One image per CTA. Output permutation is identical across images, and the PSD
// statistics (batch-mean per bin, then mean-log / log-mean over bins) are invariant
// under a fixed per-bin permutation, so no bit-reversal pass is needed.
__global__ void fft_psd_kernel(const float* __restrict__ x1, const float* __restrict__ x2) {
    extern __shared__ float2 sh[];                 // [128][PITCH]
    __shared__ float2 tw[64];                      // W_128^j, j=0..63
    int b = blockIdx.x;
    const float* src = (b < BSZ) ? (x1 + (size_t)b*NPIX) : (x2 + (size_t)(b-BSZ)*NPIX);
    int tid = threadIdx.x;

    if (tid < 64) {
        float sn, cs;
        sincospif((float)tid / 64.f, &sn, &cs);    // W = e^{-2pi i t/128} = cos - i sin
        tw[tid] = make_float2(cs, -sn);
    }
    for (int i = tid; i < NPIX; i += blockDim.x) {
        int r = i >> 7, c = i & 127;
        sh[r*PITCH + c] = make_float2(src[i], 0.f);
    }
    __syncthreads();

    // row FFTs: 128 rows x 64 butterflies = 8192 per stage
#pragma unroll
    for (int s = 0; s < 7; s++) {
        int half = 64 >> s;
        for (int bf = tid; bf < 8192; bf += blockDim.x) {
            int row = bf >> 6, t = bf & 63;
            int j = t & (half - 1);
            int blk = t >> (6 - s);
            int i0 = row*PITCH + blk*(half << 1) + j;
            int i1 = i0 + half;
            float2 u = sh[i0], v = sh[i1];
            float2 w = tw[j << s];
            float dx = u.x - v.x, dy = u.y - v.y;
            sh[i0] = make_float2(u.x + v.x, u.y + v.y);
            sh[i1] = make_float2(dx*w.x - dy*w.y, dx*w.y + dy*w.x);
        }
        __syncthreads();
    }
    // column FFTs
#pragma unroll
    for (int s = 0; s < 7; s++) {
        int half = 64 >> s;
        for (int bf = tid; bf < 8192; bf += blockDim.x) {
            int col = bf & 127, t = bf >> 7;
            int j = t & (half - 1);
            int blk = t >> (6 - s);
            int r0 = blk*(half << 1) + j;
            int i0 = r0*PITCH + col;
            int i1 = i0 + half*PITCH;
            float2 u = sh[i0], v = sh[i1];
            float2 w = tw[j << s];
            float dx = u.x - v.x, dy = u.y - v.y;
            sh[i0] = make_float2(u.x + v.x, u.y + v.y);
            sh[i1] = make_float2(dx*w.x - dy*w.y, dx*w.y + dy*w.x);
        }
        __syncthreads();
    }
    // |F|^2 -> global (coalesced)
    for (int i = tid; i < NPIX; i += blockDim.x) {
        int r = i >> 7, c = i & 127;
        float2 v = sh[r*PITCH + c];
        g_psd[(size_t)b*NPIX + i] = v.x*v.x + v.y*v.y;
    }
}

// ---------------- batch-mean PSD + partial mean-log / mean reductions ----------------
__global__ void psd_reduce_kernel() {
    int uv = blockIdx.x * 128 + threadIdx.x;
    float s = 0.f;
    for (int img = 0; img < NIMG; img++) s += g_psd[(size_t)img*NPIX + uv];
    float avg = s * (1.f / NIMG);
    __shared__ double shl[128];
    __shared__ double sha[128];
    shl[threadIdx.x] = log((double)avg);
    sha[threadIdx.x] = (double)avg;
    __syncthreads();
    for (int off = 64; off > 0; off >>= 1) {
        if (threadIdx.x < off) {
            shl[threadIdx.x] += shl[threadIdx.x + off];
            sha[threadIdx.x] += sha[threadIdx.x + off];
        }
        __syncthreads();
    }
    if (threadIdx.x == 0) { g_red_log[blockIdx.x] = shl[0]; g_red_avg[blockIdx.x] = sha[0]; }
}

// ---------------- final scalar ----------------
__global__ void final_kernel(float* __restrict__ out) {
    __shared__ double sh[128];
    int t = threadIdx.x;

    // ce = mean_i(lse_i - Dist[i,i])
    sh[t] = (double)(g_lse[t] - g_dist[t*BSZ + t]);
    __syncthreads();
    for (int off = 64; off > 0; off >>= 1) {
        if (t < off) sh[t] += sh[t + off];
        __syncthreads();
    }
    double ce = sh[0] / (double)BSZ;
    __syncthreads();

    sh[t] = g_red_log[t]; __syncthreads();
    for (int off = 64; off > 0; off >>= 1) {
        if (t < off) sh[t] += sh[t + off];
        __syncthreads();
    }
    double slog = sh[0];
    __syncthreads();

    sh[t] = g_red_avg[t]; __syncthreads();
    for (int off = 64; off > 0; off >>= 1) {
        if (t < off) sh[t] += sh[t + off];
        __syncthreads();
    }
    double savg = sh[0];

    if (t == 0) {
        double r = slog / (double)NPIX - log(savg / (double)NPIX);
        out[0] = (float)(ce - 0.1 * r);
    }
}

// ---------------- launch ----------------
extern "C" void kernel_launch(void* const* d_in, const int* in_sizes, int n_in,
                              void* d_out, int out_size) {
    const float* x1 = (const float*)d_in[0];
    const float* x2 = (const float*)d_in[1];
    float* out = (float*)d_out;

    const int smem = HW * PITCH * (int)sizeof(float2);   // 132096 B
    cudaFuncSetAttribute(fft_psd_kernel, cudaFuncAttributeMaxDynamicSharedMemorySize, smem);

    norm_kernel<<<NIMG, 256>>>(x1, x2);
    dot_kernel<<<dim3(4, 4, KSPLIT), 64>>>(x1, x2);
    dist_lse_kernel<<<BSZ, BSZ>>>();
    fft_psd_kernel<<<NIMG, 1024, smem>>>(x1, x2);
    psd_reduce_kernel<<<128, 128>>>();
    final_kernel<<<1, 128>>>(out);
}

// round 3
// speedup vs baseline: 3.0935x; 3.0935x over previous
#include <cuda_runtime.h>
#include <math.h>

#define HW     128
#define NPIX   (HW*HW)        // 16384
#define BSZ    128
#define NPACK  128            // packed complex images
#define PITCH  129            // smem row pitch in float2
#define GK     128            // GEMM K-splits (chunk = 128)

// ---------------- device scratch ----------------
__device__ float  g_norm[2*BSZ];
__device__ float  g_dot_part[GK*BSZ*BSZ];         // 8 MB partial dots
__device__ float  g_dist[BSZ*BSZ];
__device__ float  g_lse[BSZ];
__device__ float  g_psd[NPACK*NPIX];              // per packed-image |Z|^2 (8 MB)
__device__ float  g_S[NPIX];                      // sum over images of |Z|^2
__device__ double g_red_log[128];
__device__ double g_red_avg[128];

// ---------------- complex helpers ----------------
__device__ __forceinline__ float2 cadd(float2 a, float2 b){ return make_float2(a.x+b.x, a.y+b.y); }
__device__ __forceinline__ float2 csub(float2 a, float2 b){ return make_float2(a.x-b.x, a.y-b.y); }
__device__ __forceinline__ float2 cmul(float2 a, float2 b){ return make_float2(a.x*b.x - a.y*b.y, a.x*b.y + a.y*b.x); }

// radix-4 DIF butterfly with twiddles (forward, e^{-i})
__device__ __forceinline__ void r4(float2&u0,float2&u1,float2&u2,float2&u3,
                                   float2 w1, float2 w2, float2 w3){
    float2 t0 = cadd(u0,u2), t1 = csub(u0,u2);
    float2 t2 = cadd(u1,u3), t3 = csub(u1,u3);
    float2 t3m = make_float2(t3.y, -t3.x);        // -i * t3
    u0 = cadd(t0,t2);
    u1 = cmul(cadd(t1,t3m), w1);
    u2 = cmul(csub(t0,t2), w2);
    u3 = cmul(csub(t1,t3m), w3);
}
__device__ __forceinline__ void r4nw(float2&u0,float2&u1,float2&u2,float2&u3){
    float2 t0 = cadd(u0,u2), t1 = csub(u0,u2);
    float2 t2 = cadd(u1,u3), t3 = csub(u1,u3);
    float2 t3m = make_float2(t3.y, -t3.x);
    u0 = cadd(t0,t2);
    u1 = cadd(t1,t3m);
    u2 = csub(t0,t2);
    u3 = csub(t1,t3m);
}
__device__ __forceinline__ void r2(float2&u0,float2&u1){
    float2 a = cadd(u0,u1), b = csub(u0,u1);
    u0 = a; u1 = b;
}

// DIF digit-reversal permutation for stage order (radix 4,4,4,2):
// stored index p = 32q1+8q2+2q3+q4 holds frequency sig(p)=q1+4q2+16q3+64q4
__device__ __forceinline__ int sigp(int p){
    return (p>>5) + (((p>>3)&3)<<2) + (((p>>1)&3)<<4) + ((p&1)<<6);
}
__device__ __forceinline__ int isigp(int k){
    return ((k&3)<<5) + (((k>>2)&3)<<3) + (((k>>4)&3)<<1) + (k>>6);
}
__device__ __forceinline__ int tau(int p){
    return isigp((128 - sigp(p)) & 127);
}

// ---------------- squared norms ----------------
__global__ void norm_kernel(const float* __restrict__ x1, const float* __restrict__ x2) {
    int b = blockIdx.x;
    const float* src = (b < BSZ) ? (x1 + (size_t)b*NPIX) : (x2 + (size_t)(b-BSZ)*NPIX);
    float s = 0.f;
    for (int i = threadIdx.x; i < NPIX; i += blockDim.x) { float v = src[i]; s += v*v; }
    __shared__ float red[256];
    red[threadIdx.x] = s; __syncthreads();
    for (int off = 128; off > 0; off >>= 1) {
        if (threadIdx.x < off) red[threadIdx.x] += red[threadIdx.x + off];
        __syncthreads();
    }
    if (threadIdx.x == 0) g_norm[b] = red[0];
}

// ---------------- GEMM: dot(a_i, b_j), 128x128xK, K-split 128 ----------------
// grid (2, 1, GK): blockIdx.x = 64-wide N tile, blockIdx.z = K chunk of 128.
// block 256 threads, 8x4 micro-tile -> 128x64 per block.
__global__ __launch_bounds__(256) void dot_kernel(const float* __restrict__ A, const float* __restrict__ B) {
    __shared__ float As[16][132];
    __shared__ float Bs[16][68];
    int tid = threadIdx.x;
    int tx = tid & 15, ty = tid >> 4;
    int nb = blockIdx.x * 64;
    int k0 = blockIdx.z * 128;

    float acc[8][4];
#pragma unroll
    for (int r = 0; r < 8; r++)
#pragma unroll
        for (int c = 0; c < 4; c++) acc[r][c] = 0.f;

    for (int ks = 0; ks < 8; ks++) {
        int kb = k0 + ks * 16;
        __syncthreads();
        // load A tile 128x16 (2 float4 per thread)
#pragma unroll
        for (int i = 0; i < 2; i++) {
            int idx = tid + i * 256;
            int row = idx >> 2, kq = idx & 3;
            float4 v = *reinterpret_cast<const float4*>(A + (size_t)row * NPIX + kb + kq * 4);
            As[kq*4+0][row] = v.x; As[kq*4+1][row] = v.y;
            As[kq*4+2][row] = v.z; As[kq*4+3][row] = v.w;
        }
        // load B tile 64x16 (1 float4 per thread)
        {
            int row = tid >> 2, kq = tid & 3;
            float4 v = *reinterpret_cast<const float4*>(B + (size_t)(nb + row) * NPIX + kb + kq * 4);
            Bs[kq*4+0][row] = v.x; Bs[kq*4+1][row] = v.y;
            Bs[kq*4+2][row] = v.z; Bs[kq*4+3][row] = v.w;
        }
        __syncthreads();
#pragma unroll
        for (int kk = 0; kk < 16; kk++) {
            float4 a0 = *reinterpret_cast<const float4*>(&As[kk][ty*8]);
            float4 a1 = *reinterpret_cast<const float4*>(&As[kk][ty*8+4]);
            float4 b0 = *reinterpret_cast<const float4*>(&Bs[kk][tx*4]);
            float ra[8] = {a0.x,a0.y,a0.z,a0.w,a1.x,a1.y,a1.z,a1.w};
            float rb[4] = {b0.x,b0.y,b0.z,b0.w};
#pragma unroll
            for (int r = 0; r < 8; r++)
#pragma unroll
                for (int c = 0; c < 4; c++) acc[r][c] += ra[r] * rb[c];
        }
    }
    float* outp = g_dot_part + (size_t)blockIdx.z * BSZ * BSZ;
#pragma unroll
    for (int r = 0; r < 8; r++) {
        float4 v = make_float4(acc[r][0], acc[r][1], acc[r][2], acc[r][3]);
        *reinterpret_cast<float4*>(outp + (ty*8 + r) * BSZ + nb + tx*4) = v;
    }
}

// ---------------- Dist + per-row logsumexp ----------------
__global__ void dist_lse_kernel() {
    int i = blockIdx.x, j = threadIdx.x;
    float dot = 0.f;
#pragma unroll 8
    for (int s = 0; s < GK; s++) dot += g_dot_part[(size_t)s*BSZ*BSZ + i*BSZ + j];
    float d2 = g_norm[i] + g_norm[BSZ + j] - 2.f * dot;
    float d = sqrtf(fmaxf(d2, 0.f));
    g_dist[i*BSZ + j] = d;

    __shared__ float red[BSZ];
    red[j] = d; __syncthreads();
    for (int off = 64; off > 0; off >>= 1) {
        if (j < off) red[j] = fmaxf(red[j], red[j + off]);
        __syncthreads();
    }
    float mx = red[0]; __syncthreads();
    red[j] = expf(d - mx); __syncthreads();
    for (int off = 64; off > 0; off >>= 1) {
        if (j < off) red[j] += red[j + off];
        __syncthreads();
    }
    if (j == 0) g_lse[i] = mx + logf(red[0]);
}

// ---------------- packed 2D FFT (radix-4 DIF, digit-reversed out) + |Z|^2 ----------------
// One packed image z = x1[b] + i*x2[b] per CTA; 128 CTAs (one wave).
__global__ __launch_bounds__(1024) void fft_psd_kernel(const float* __restrict__ x1, const float* __restrict__ x2) {
    extern __shared__ float2 sh[];                 // [128][PITCH]
    __shared__ float2 tw[128];                     // W_128^j = e^{-2pi i j/128}
    int b = blockIdx.x;
    const float* sa = x1 + (size_t)b*NPIX;
    const float* sb = x2 + (size_t)b*NPIX;
    int tid = threadIdx.x;

    if (tid < 128) {
        float sn, cs;
        sincospif((float)tid / 64.f, &sn, &cs);
        tw[tid] = make_float2(cs, -sn);
    }
    for (int i = tid; i < NPIX; i += 1024) {
        int r = i >> 7, c = i & 127;
        sh[r*PITCH + c] = make_float2(sa[i], sb[i]);
    }
    __syncthreads();

    // ---- rows: pass A (L=128) ----
#pragma unroll
    for (int it = 0; it < 4; it++) {
        int bf = tid + it*1024;
        int row = bf >> 5, j = bf & 31;
        int base = row*PITCH + j;
        float2 u0 = sh[base], u1 = sh[base+32], u2 = sh[base+64], u3 = sh[base+96];
        r4(u0, u1, u2, u3, tw[j], tw[2*j], tw[3*j]);
        sh[base] = u0; sh[base+32] = u1; sh[base+64] = u2; sh[base+96] = u3;
    }
    __syncthreads();
    // ---- rows: pass B (L=32) ----
#pragma unroll
    for (int it = 0; it < 4; it++) {
        int bf = tid + it*1024;
        int row = bf >> 5, t = bf & 31;
        int blk = t >> 3, j = t & 7;
        int base = row*PITCH + blk*32 + j;
        float2 u0 = sh[base], u1 = sh[base+8], u2 = sh[base+16], u3 = sh[base+24];
        r4(u0, u1, u2, u3, tw[4*j], tw[8*j], tw[12*j]);
        sh[base] = u0; sh[base+8] = u1; sh[base+16] = u2; sh[base+24] = u3;
    }
    __syncthreads();
    // ---- rows: pass C (L=8 radix-4 + L=2 radix-2, in registers) ----
#pragma unroll
    for (int it = 0; it < 2; it++) {
        int g = tid + it*1024;
        int row = g & 127, oct = g >> 7;
        int base = row*PITCH + oct*8;
        float2 v0 = sh[base+0], v1 = sh[base+1], v2 = sh[base+2], v3 = sh[base+3];
        float2 v4 = sh[base+4], v5 = sh[base+5], v6 = sh[base+6], v7 = sh[base+7];
        r4nw(v0, v2, v4, v6);
        r4(v1, v3, v5, v7, tw[16], tw[32], tw[48]);
        r2(v0, v1); r2(v2, v3); r2(v4, v5); r2(v6, v7);
        sh[base+0] = v0; sh[base+1] = v1; sh[base+2] = v2; sh[base+3] = v3;
        sh[base+4] = v4; sh[base+5] = v5; sh[base+6] = v6; sh[base+7] = v7;
    }
    __syncthreads();

    // ---- cols: pass A ----
#pragma unroll
    for (int it = 0; it < 4; it++) {
        int bf = tid + it*1024;
        int col = bf & 127, j = bf >> 7;
        int base = j*PITCH + col;
        float2 u0 = sh[base], u1 = sh[base+32*PITCH], u2 = sh[base+64*PITCH], u3 = sh[base+96*PITCH];
        r4(u0, u1, u2, u3, tw[j], tw[2*j], tw[3*j]);
        sh[base] = u0; sh[base+32*PITCH] = u1; sh[base+64*PITCH] = u2; sh[base+96*PITCH] = u3;
    }
    __syncthreads();
    // ---- cols: pass B ----
#pragma unroll
    for (int it = 0; it < 4; it++) {
        int bf = tid + it*1024;
        int col = bf & 127, t = bf >> 7;
        int blk = t >> 3, j = t & 7;
        int base = (blk*32 + j)*PITCH + col;
        float2 u0 = sh[base], u1 = sh[base+8*PITCH], u2 = sh[base+16*PITCH], u3 = sh[base+24*PITCH];
        r4(u0, u1, u2, u3, tw[4*j], tw[8*j], tw[12*j]);
        sh[base] = u0; sh[base+8*PITCH] = u1; sh[base+16*PITCH] = u2; sh[base+24*PITCH] = u3;
    }
    __syncthreads();
    // ---- cols: pass C ----
#pragma unroll
    for (int it = 0; it < 2; it++) {
        int g = tid + it*1024;
        int col = g & 127, oct = g >> 7;
        int base = (oct*8)*PITCH + col;
        float2 v0 = sh[base+0*PITCH], v1 = sh[base+1*PITCH], v2 = sh[base+2*PITCH], v3 = sh[base+3*PITCH];
        float2 v4 = sh[base+4*PITCH], v5 = sh[base+5*PITCH], v6 = sh[base+6*PITCH], v7 = sh[base+7*PITCH];
        r4nw(v0, v2, v4, v6);
        r4(v1, v3, v5, v7, tw[16], tw[32], tw[48]);
        r2(v0, v1); r2(v2, v3); r2(v4, v5); r2(v6, v7);
        sh[base+0*PITCH] = v0; sh[base+1*PITCH] = v1; sh[base+2*PITCH] = v2; sh[base+3*PITCH] = v3;
        sh[base+4*PITCH] = v4; sh[base+5*PITCH] = v5; sh[base+6*PITCH] = v6; sh[base+7*PITCH] = v7;
    }
    __syncthreads();

    for (int i = tid; i < NPIX; i += 1024) {
        int r = i >> 7, c = i & 127;
        float2 v = sh[r*PITCH + c];
        g_psd[(size_t)b*NPIX + i] = v.x*v.x + v.y*v.y;
    }
}

// ---------------- S(p) = sum over packed images of |Z|^2 ----------------
__global__ void psd_reduce_kernel() {
    int p = blockIdx.x * 128 + threadIdx.x;
    float s = 0.f;
    for (int img = 0; img < NPACK; img++) s += g_psd[(size_t)img*NPIX + p];
    g_S[p] = s;
}

// ---------------- per-bin avgpsd via -k pairing, partial stats ----------------
__global__ void psd_stats_kernel() {
    int p = blockIdx.x * 128 + threadIdx.x;
    int pr = p >> 7, pc = p & 127;
    int q = tau(pr) * 128 + tau(pc);
    double avg = ((double)g_S[p] + (double)g_S[q]) * (1.0 / 512.0);
    __shared__ double shl[128];
    __shared__ double sha[128];
    shl[threadIdx.x] = log(avg);
    sha[threadIdx.x] = avg;
    __syncthreads();
    for (int off = 64; off > 0; off >>= 1) {
        if (threadIdx.x < off) {
            shl[threadIdx.x] += shl[threadIdx.x + off];
            sha[threadIdx.x] += sha[threadIdx.x + off];
        }
        __syncthreads();
    }
    if (threadIdx.x == 0) { g_red_log[blockIdx.x] = shl[0]; g_red_avg[blockIdx.x] = sha[0]; }
}

// ---------------- final scalar ----------------
__global__ void final_kernel(float* __restrict__ out) {
    __shared__ double sh[128];
    int t = threadIdx.x;

    sh[t] = (double)(g_lse[t] - g_dist[t*BSZ + t]);
    __syncthreads();
    for (int off = 64; off > 0; off >>= 1) {
        if (t < off) sh[t] += sh[t + off];
        __syncthreads();
    }
    double ce = sh[0] / (double)BSZ;
    __syncthreads();

    sh[t] = g_red_log[t]; __syncthreads();
    for (int off = 64; off > 0; off >>= 1) {
        if (t < off) sh[t] += sh[t + off];
        __syncthreads();
    }
    double slog = sh[0];
    __syncthreads();

    sh[t] = g_red_avg[t]; __syncthreads();
    for (int off = 64; off > 0; off >>= 1) {
        if (t < off) sh[t] += sh[t + off];
        __syncthreads();
    }
    double savg = sh[0];

    if (t == 0) {
        double r = slog / (double)NPIX - log(savg / (double)NPIX);
        out[0] = (float)(ce - 0.1 * r);
    }
}

// ---------------- launch ----------------
extern "C" void kernel_launch(void* const* d_in, const int* in_sizes, int n_in,
                              void* d_out, int out_size) {
    const float* x1 = (const float*)d_in[0];
    const float* x2 = (const float*)d_in[1];
    float* out = (float*)d_out;

    const int smem = HW * PITCH * (int)sizeof(float2);   // 132096 B
    cudaFuncSetAttribute(fft_psd_kernel, cudaFuncAttributeMaxDynamicSharedMemorySize, smem);

    norm_kernel<<<2*BSZ, 256>>>(x1, x2);
    dot_kernel<<<dim3(2, 1, GK), 256>>>(x1, x2);
    dist_lse_kernel<<<BSZ, BSZ>>>();
    fft_psd_kernel<<<NPACK, 1024, smem>>>(x1, x2);
    psd_reduce_kernel<<<128, 128>>>();
    psd_stats_kernel<<<128, 128>>>();
    final_kernel<<<1, 128>>>(out);
}